// round 14
// baseline (speedup 1.0000x reference)
#include <cuda_runtime.h>
#include <cstdint>

#define D_DIM 64
#define BT 64
#define NT 64
#define TPB 256
#define XSTRIDE 68
#define ASTRIDE 68

__device__ __forceinline__ uint64_t pk2(float lo, float hi) {
    uint64_t r; asm("mov.b64 %0, {%1, %2};" : "=l"(r) : "f"(lo), "f"(hi)); return r;
}
__device__ __forceinline__ void upk2(uint64_t v, float& lo, float& hi) {
    asm("mov.b64 {%0, %1}, %2;" : "=f"(lo), "=f"(hi) : "l"(v));
}
__device__ __forceinline__ uint64_t fma2(uint64_t a, uint64_t b, uint64_t c) {
    uint64_t d; asm("fma.rn.f32x2 %0, %1, %2, %3;" : "=l"(d) : "l"(a), "l"(b), "l"(c)); return d;
}
__device__ __forceinline__ uint64_t mul2(uint64_t a, uint64_t b) {
    uint64_t d; asm("mul.rn.f32x2 %0, %1, %2;" : "=l"(d) : "l"(a), "l"(b)); return d;
}

extern __shared__ float smem_dyn[];

// One fused step: 4 dims of half A (d0..d0+3) AND 4 dims of half B (d0+32..d0+35).
// 2x independent dependency chains per accumulator class.
__device__ __forceinline__ void do_dblk2(const float* __restrict__ xrow,
                                         const float* __restrict__ arow,
                                         const float* __restrict__ brow,
                                         int d0, uint64_t M1,
                                         float (&sA0)[4][2], float (&sA1)[4][2], uint64_t (&pA)[4][2],
                                         float (&sB0)[4][2], float (&sB1)[4][2], uint64_t (&pB)[4][2])
{
    float xqA[4][4], xqB[4][4];
    #pragma unroll
    for (int bi = 0; bi < 4; bi++) {
        float4 va = *reinterpret_cast<const float4*>(xrow + bi * XSTRIDE + d0);
        float4 vb = *reinterpret_cast<const float4*>(xrow + bi * XSTRIDE + d0 + 32);
        xqA[bi][0] = va.x; xqA[bi][1] = va.y; xqA[bi][2] = va.z; xqA[bi][3] = va.w;
        xqB[bi][0] = vb.x; xqB[bi][1] = vb.y; xqB[bi][2] = vb.z; xqB[bi][3] = vb.w;
    }
    #pragma unroll
    for (int dd = 0; dd < 4; dd++) {
        const int offA = (d0 + dd) * ASTRIDE;
        const int offB = offA + 32 * ASTRIDE;
        const ulonglong2 avA = *reinterpret_cast<const ulonglong2*>(arow + offA);
        const ulonglong2 bvA = *reinterpret_cast<const ulonglong2*>(brow + offA);
        const ulonglong2 avB = *reinterpret_cast<const ulonglong2*>(arow + offB);
        const ulonglong2 bvB = *reinterpret_cast<const ulonglong2*>(brow + offB);
        const uint64_t AA[2] = {avA.x, avA.y}, BA[2] = {bvA.x, bvA.y};
        const uint64_t AB[2] = {avB.x, avB.y}, BB[2] = {bvB.x, bvB.y};
        #pragma unroll
        for (int bi = 0; bi < 4; bi++) {
            const uint64_t xpA = pk2(xqA[bi][dd], xqA[bi][dd]);
            const uint64_t xpB = pk2(xqB[bi][dd], xqB[bi][dd]);
            #pragma unroll
            for (int k = 0; k < 2; k++) {
                uint64_t zA = fma2(xpA, AA[k], BA[k]);
                uint64_t zB = fma2(xpB, AB[k], BB[k]);
                uint64_t wA = fma2(zA, zA, M1);        // z^2 - 1
                uint64_t wB = fma2(zB, zB, M1);
                float a0, a1, b0, b1;
                upk2(wA, a0, a1);
                upk2(wB, b0, b1);
                sA0[bi][k] += a0; sA1[bi][k] += a1;    // scalar FADDs (R8 win)
                sB0[bi][k] += b0; sB1[bi][k] += b1;
                pA[bi][k] = mul2(pA[bi][k], wA);
                pB[bi][k] = mul2(pB[bi][k], wB);
            }
        }
    }
}

__global__ __launch_bounds__(TPB, 2)
void wavelet_kernel(const float* __restrict__ x,
                    const float* __restrict__ centers,
                    const float* __restrict__ scales,
                    float* __restrict__ out, int N)
{
    float* sx = smem_dyn;                   // [BT][XSTRIDE]
    float* sa = sx + BT * XSTRIDE;          // [D][ASTRIDE]  1/s
    float* sb = sa + D_DIM * ASTRIDE;       // [D][ASTRIDE]  -c/s

    const int tid = threadIdx.x;
    const int b0 = blockIdx.x * BT;
    const int n0 = blockIdx.y * NT;

    #pragma unroll 2
    for (int i = tid; i < BT * D_DIM; i += TPB) {
        int r = i >> 6, c = i & 63;
        sx[r * XSTRIDE + c] = x[(b0 + r) * D_DIM + c];
    }
    #pragma unroll 4
    for (int i = tid; i < NT * D_DIM; i += TPB) {
        int d = i & 63, n = i >> 6;
        int g = (n0 + n) * D_DIM + d;
        float inv = 1.0f / scales[g];
        sa[d * ASTRIDE + n] = inv;
        sb[d * ASTRIDE + n] = -centers[g] * inv;
    }
    __syncthreads();

    const int ng = tid & 15;
    const int bg = tid >> 4;
    const int rot = (tid >> 5) & 7;        // warp desync (R13, free)

    const float* xrow = sx + (bg * 4) * XSTRIDE;
    const float* arow = sa + ng * 4;
    const float* brow = sb + ng * 4;

    const uint64_t M1 = pk2(-1.0f, -1.0f);
    float sA0[4][2], sA1[4][2], sB0[4][2], sB1[4][2];
    uint64_t pA[4][2], pB[4][2];
    #pragma unroll
    for (int bi = 0; bi < 4; bi++)
        #pragma unroll
        for (int k = 0; k < 2; k++) {
            sA0[bi][k] = sA1[bi][k] = sB0[bi][k] = sB1[bi][k] = 0.0f;
            pA[bi][k] = pk2(1.f, 1.f);
            pB[bi][k] = pk2(1.f, 1.f);
        }

    // fused halves: per q, dims (d0..d0+3) and (d0+32..d0+35)
    #pragma unroll 2
    for (int q = 0; q < 8; q++)
        do_dblk2(xrow, arow, brow, ((q + rot) & 7) * 4, M1,
                 sA0, sA1, pA, sB0, sB1, pB);

    // epilogue: per half, h = p * exp(-0.5*(sum_w + 32)); combine multiplicatively.
    // |psi| <= 1 per element, so each half's h is bounded; product is safe.
    float* orow = out + (long)(b0 + bg * 4) * N + n0 + ng * 4;
    #pragma unroll
    for (int bi = 0; bi < 4; bi++) {
        float h[4];
        #pragma unroll
        for (int k = 0; k < 2; k++) {
            float pa0, pa1, pb0, pb1;
            upk2(pA[bi][k], pa0, pa1);
            upk2(pB[bi][k], pb0, pb1);
            float hA0 = pa0 * __expf(-0.5f * (sA0[bi][k] + 32.0f));
            float hA1 = pa1 * __expf(-0.5f * (sA1[bi][k] + 32.0f));
            float hB0 = pb0 * __expf(-0.5f * (sB0[bi][k] + 32.0f));
            float hB1 = pb1 * __expf(-0.5f * (sB1[bi][k] + 32.0f));
            h[2 * k]     = hA0 * hB0;
            h[2 * k + 1] = hA1 * hB1;
        }
        float4 v = {h[0], h[1], h[2], h[3]};
        *reinterpret_cast<float4*>(orow + (long)bi * N) = v;
    }
}

extern "C" void kernel_launch(void* const* d_in, const int* in_sizes, int n_in,
                              void* d_out, int out_size)
{
    const float* x       = (const float*)d_in[0];
    const float* centers = (const float*)d_in[1];
    const float* scales  = (const float*)d_in[2];
    float* out = (float*)d_out;

    const int B = in_sizes[0] / D_DIM;   // 8192
    const int N = in_sizes[1] / D_DIM;   // 512

    const int smem_bytes = (BT * XSTRIDE + 2 * D_DIM * ASTRIDE) * sizeof(float); // 52224
    static bool attr_set = false;
    if (!attr_set) {
        cudaFuncSetAttribute(wavelet_kernel,
                             cudaFuncAttributeMaxDynamicSharedMemorySize, smem_bytes);
        attr_set = true;
    }

    dim3 grid(B / BT, N / NT);           // (128, 8) = 1024 blocks
    wavelet_kernel<<<grid, TPB, smem_bytes>>>(x, centers, scales, out, N);
}

// round 15
// speedup vs baseline: 1.1187x; 1.1187x over previous
#include <cuda_runtime.h>
#include <cstdint>

#define D_DIM 64
#define BT 64
#define NT 64
#define TPB 256
#define XSTRIDE 68
#define ASTRIDE 68

__device__ __forceinline__ uint64_t pk2(float lo, float hi) {
    uint64_t r; asm("mov.b64 %0, {%1, %2};" : "=l"(r) : "f"(lo), "f"(hi)); return r;
}
__device__ __forceinline__ void upk2(uint64_t v, float& lo, float& hi) {
    asm("mov.b64 {%0, %1}, %2;" : "=f"(lo), "=f"(hi) : "l"(v));
}
__device__ __forceinline__ uint64_t fma2(uint64_t a, uint64_t b, uint64_t c) {
    uint64_t d; asm("fma.rn.f32x2 %0, %1, %2, %3;" : "=l"(d) : "l"(a), "l"(b), "l"(c)); return d;
}
__device__ __forceinline__ uint64_t mul2(uint64_t a, uint64_t b) {
    uint64_t d; asm("mul.rn.f32x2 %0, %1, %2;" : "=l"(d) : "l"(a), "l"(b)); return d;
}

extern __shared__ float smem_dyn[];

// One 4-dim block at reduced register footprint: dd handled in 2 pairs,
// x staged as float2 per (bi, pair) -> xq 8 regs instead of 16.
__device__ __forceinline__ void do_dblk(const float* __restrict__ xrow,
                                        const float* __restrict__ arow,
                                        const float* __restrict__ brow,
                                        int dblk, uint64_t M1,
                                        float (&s0)[4][2], float (&s1)[4][2],
                                        uint64_t (&pacc)[4][2])
{
    #pragma unroll
    for (int dp = 0; dp < 2; dp++) {
        const int d0 = dblk + 2 * dp;
        // stage x: one float2 per b-row (4 LDS.64)
        float2 xq[4];
        #pragma unroll
        for (int bi = 0; bi < 4; bi++)
            xq[bi] = *reinterpret_cast<const float2*>(xrow + bi * XSTRIDE + d0);

        #pragma unroll
        for (int dd = 0; dd < 2; dd++) {
            const int off = (d0 + dd) * ASTRIDE;
            const ulonglong2 av = *reinterpret_cast<const ulonglong2*>(arow + off);
            const ulonglong2 bv = *reinterpret_cast<const ulonglong2*>(brow + off);
            const uint64_t A[2]  = {av.x, av.y};
            const uint64_t Bv[2] = {bv.x, bv.y};
            #pragma unroll
            for (int bi = 0; bi < 4; bi++) {
                const float xs = dd ? xq[bi].y : xq[bi].x;
                const uint64_t xp = pk2(xs, xs);
                #pragma unroll
                for (int k = 0; k < 2; k++) {
                    uint64_t z = fma2(xp, A[k], Bv[k]);
                    uint64_t w = fma2(z, z, M1);          // z^2 - 1
                    float w0, w1;
                    upk2(w, w0, w1);                      // pair-alias, no MOVs
                    s0[bi][k] += w0;                      // scalar FADDs
                    s1[bi][k] += w1;                      // sum z^2 = sum w + count
                    pacc[bi][k] = mul2(pacc[bi][k], w);
                }
            }
        }
    }
}

__global__ __launch_bounds__(TPB, 4)
void wavelet_kernel(const float* __restrict__ x,
                    const float* __restrict__ centers,
                    const float* __restrict__ scales,
                    float* __restrict__ out, int N)
{
    float* sx = smem_dyn;                   // [BT][XSTRIDE]
    float* sa = sx + BT * XSTRIDE;          // [D][ASTRIDE]  1/s (d-major)
    float* sb = sa + D_DIM * ASTRIDE;       // [D][ASTRIDE]  -c/s

    const int tid = threadIdx.x;
    const int b0 = blockIdx.x * BT;
    const int n0 = blockIdx.y * NT;

    #pragma unroll 2
    for (int i = tid; i < BT * D_DIM; i += TPB) {
        int r = i >> 6, c = i & 63;
        sx[r * XSTRIDE + c] = x[(b0 + r) * D_DIM + c];
    }
    #pragma unroll 4
    for (int i = tid; i < NT * D_DIM; i += TPB) {
        int d = i & 63, n = i >> 6;
        int g = (n0 + n) * D_DIM + d;
        float inv = 1.0f / scales[g];
        sa[d * ASTRIDE + n] = inv;
        sb[d * ASTRIDE + n] = -centers[g] * inv;
    }
    __syncthreads();

    const int ng = tid & 15;           // 4 n's at ng*4
    const int bg = tid >> 4;           // 4 b's at bg*4
    const int rot = (tid >> 5) & 7;    // warp desync (R13)

    const float* xrow = sx + (bg * 4) * XSTRIDE;
    const float* arow = sa + ng * 4;
    const float* brow = sb + ng * 4;

    const uint64_t M1 = pk2(-1.0f, -1.0f);
    float s0[4][2], s1[4][2];
    uint64_t pacc[4][2];
    #pragma unroll
    for (int bi = 0; bi < 4; bi++)
        #pragma unroll
        for (int k = 0; k < 2; k++) {
            s0[bi][k] = 0.0f; s1[bi][k] = 0.0f;
            pacc[bi][k] = pk2(1.f, 1.f);
        }

    // first half: d = 0..31, warp-rotated order
    #pragma unroll 2
    for (int q = 0; q < 8; q++)
        do_dblk(xrow, arow, brow, ((q + rot) & 7) * 4, M1, s0, s1, pacc);

    // range-control fold
    #pragma unroll
    for (int bi = 0; bi < 4; bi++)
        #pragma unroll
        for (int k = 0; k < 2; k++) {
            float p0, p1;
            upk2(pacc[bi][k], p0, p1);
            p0 *= __expf(-0.5f * (s0[bi][k] + 32.0f));
            p1 *= __expf(-0.5f * (s1[bi][k] + 32.0f));
            pacc[bi][k] = pk2(p0, p1);
            s0[bi][k] = 0.0f; s1[bi][k] = 0.0f;
        }

    // second half: d = 32..63
    #pragma unroll 2
    for (int q = 0; q < 8; q++)
        do_dblk(xrow, arow, brow, 32 + ((q + rot) & 7) * 4, M1, s0, s1, pacc);

    // epilogue
    float* orow = out + (long)(b0 + bg * 4) * N + n0 + ng * 4;
    #pragma unroll
    for (int bi = 0; bi < 4; bi++) {
        float h[4];
        #pragma unroll
        for (int k = 0; k < 2; k++) {
            float p0, p1;
            upk2(pacc[bi][k], p0, p1);
            h[2 * k]     = p0 * __expf(-0.5f * (s0[bi][k] + 32.0f));
            h[2 * k + 1] = p1 * __expf(-0.5f * (s1[bi][k] + 32.0f));
        }
        float4 v = {h[0], h[1], h[2], h[3]};
        *reinterpret_cast<float4*>(orow + (long)bi * N) = v;
    }
}

extern "C" void kernel_launch(void* const* d_in, const int* in_sizes, int n_in,
                              void* d_out, int out_size)
{
    const float* x       = (const float*)d_in[0];
    const float* centers = (const float*)d_in[1];
    const float* scales  = (const float*)d_in[2];
    float* out = (float*)d_out;

    const int B = in_sizes[0] / D_DIM;   // 8192
    const int N = in_sizes[1] / D_DIM;   // 512

    const int smem_bytes = (BT * XSTRIDE + 2 * D_DIM * ASTRIDE) * sizeof(float); // 52224
    static bool attr_set = false;
    if (!attr_set) {
        cudaFuncSetAttribute(wavelet_kernel,
                             cudaFuncAttributeMaxDynamicSharedMemorySize, smem_bytes);
        attr_set = true;
    }

    dim3 grid(B / BT, N / NT);           // (128, 8) = 1024 blocks
    wavelet_kernel<<<grid, TPB, smem_bytes>>>(x, centers, scales, out, N);
}